// round 1
// baseline (speedup 1.0000x reference)
#include <cuda_runtime.h>
#include <cuda_bf16.h>
#include <math.h>

#define Bdim 16
#define Hdim 128
#define Wdim 128
#define Cdim 64
#define C2d  128
#define Tsteps 16
#define Mrows (Bdim*Hdim*Wdim)      // 262144
#define BM 64
#define NTILES (Mrows/BM)           // 4096
#define THREADS 512

// Scratch: DFT'd (and A-scaled) convolution fields, layout [h][w][c]
__device__ float g_Ar[Hdim*Wdim*Cdim];
__device__ float g_Ai[Hdim*Wdim*Cdim];
__device__ float g_Br[Hdim*Wdim*Cdim];
__device__ float g_Bi[Hdim*Wdim*Cdim];

// ---------------- f32x2 helpers (sm_100+) ----------------
static __device__ __forceinline__ unsigned long long splat2(float x){
    unsigned long long r; asm("mov.b64 %0, {%1, %1};" : "=l"(r) : "f"(x)); return r;
}
static __device__ __forceinline__ unsigned long long pack2(float lo, float hi){
    unsigned long long r; asm("mov.b64 %0, {%1, %2};" : "=l"(r) : "f"(lo), "f"(hi)); return r;
}
static __device__ __forceinline__ void unpack2(unsigned long long v, float& lo, float& hi){
    asm("mov.b64 {%0, %1}, %2;" : "=f"(lo), "=f"(hi) : "l"(v));
}
static __device__ __forceinline__ unsigned long long fma2(unsigned long long a, unsigned long long b, unsigned long long c){
    unsigned long long d; asm("fma.rn.f32x2 %0, %1, %2, %3;" : "=l"(d) : "l"(a), "l"(b), "l"(c)); return d;
}
static __device__ __forceinline__ unsigned long long mul2(unsigned long long a, unsigned long long b){
    unsigned long long d; asm("mul.rn.f32x2 %0, %1, %2;" : "=l"(d) : "l"(a), "l"(b)); return d;
}

static __device__ __forceinline__ float sigmoidf_(float x){
    return __fdividef(1.0f, 1.0f + __expf(-x));
}
static __device__ __forceinline__ float softplusf_(float x){
    return fmaxf(x, 0.0f) + __logf(1.0f + __expf(-fabsf(x)));
}

// ---------------- Kernel 0: 49-tap DFT of padded 7x7 kernels ----------------
// F[c][u][v] = sum_{p,q} kern[c][p][q] * exp(-2pi i (u(p+60)+v(q+60))/128)
// A gets the stable-scale applied; B stored raw.
__global__ void dft_kernel(const float* __restrict__ A_real, const float* __restrict__ A_imag,
                           const float* __restrict__ B_real, const float* __restrict__ B_imag){
    __shared__ float twc[128], tws[128];
    int t = threadIdx.x;
    for (int tt = t; tt < 128; tt += 64){
        float s, c; sincospif((float)tt / 64.0f, &s, &c);
        twc[tt] = c; tws[tt] = -s;          // exp(-i*2pi*tt/128)
    }
    __syncthreads();
    const int v = blockIdx.x, u = blockIdx.y;
    const int c = t;                         // 0..63
    float fra = 0.f, fia = 0.f, frb = 0.f, fib = 0.f;
#pragma unroll
    for (int p = 0; p < 7; p++){
        int iu = u * (p + 60);
#pragma unroll
        for (int q = 0; q < 7; q++){
            int idx = (iu + v * (q + 60)) & 127;
            float cr = twc[idx], ci = tws[idx];
            int ki = c*49 + p*7 + q;
            float ar = A_real[ki], ai = A_imag[ki];
            float br = B_real[ki], bi = B_imag[ki];
            fra += ar*cr - ai*ci;  fia += ar*ci + ai*cr;
            frb += br*cr - bi*ci;  fib += br*ci + bi*cr;
        }
    }
    float mag = sqrtf(fra*fra + fia*fia + 1e-8f);
    float sc  = 0.95f * sigmoidf_(mag) / (mag + 1e-8f);
    int o = (u*Wdim + v)*Cdim + c;
    g_Ar[o] = fra * sc;  g_Ai[o] = fia * sc;
    g_Br[o] = frb;       g_Bi[o] = fib;
}

// ---------------- Kernel 1: persistent fused gates-GEMM + recurrence ----------------
// smem: ws2 = 3*64*64 float4 = 192KB ((re,im)-paired weights, XOR swizzled), xs = 64x128 f32 = 32KB
__global__ void __launch_bounds__(THREADS, 1)
main_kernel(const float* __restrict__ x,
            const float* __restrict__ Wf, const float* __restrict__ bf,
            const float* __restrict__ Wi, const float* __restrict__ bip,
            const float* __restrict__ Wd, const float* __restrict__ bd,
            float* __restrict__ out){
    extern __shared__ float smem[];
    float4* ws2 = (float4*)smem;             // 12288 float4
    float*  xs  = smem + 4*12288;            // 8192 floats

    const int tid = threadIdx.x;
    const int tn  = tid & 63;                // channel 0..63 (warp lanes -> consecutive tn)
    const int rg  = tid >> 6;                // row group 0..7 (constant within warp)
    const int sw  = tn & 31;

    // Stage paired, swizzled weights once per (persistent) block.
    // ws2[((m*64+c)<<6) + (k2 ^ (c&31))] = {Wm[2k2][c], Wm[2k2][c+64], Wm[2k2+1][c], Wm[2k2+1][c+64]}
    for (int idx = tid; idx < 3*64*64; idx += THREADS){
        int m   = idx >> 12;
        int rem = idx & 4095;
        int k2  = rem >> 6;
        int c   = rem & 63;
        const float* Wm = (m == 0) ? Wf : ((m == 1) ? Wi : Wd);
        float4 v;
        v.x = Wm[(2*k2  )*128 + c];
        v.y = Wm[(2*k2  )*128 + c + 64];
        v.z = Wm[(2*k2+1)*128 + c];
        v.w = Wm[(2*k2+1)*128 + c + 64];
        ws2[((m*64 + c) << 6) + (k2 ^ (c & 31))] = v;
    }

    const float bf_lo = bf[tn],  bf_hi = bf[tn+64];
    const float bi_lo = bip[tn], bi_hi = bip[tn+64];
    const float bd_lo = bd[tn],  bd_hi = bd[tn+64];

    for (int tile = blockIdx.x; tile < NTILES; tile += gridDim.x){
        __syncthreads();   // also covers first-iteration ws2 readiness
        // Load X tile (64 rows x 128 floats), coalesced float4
        {
            const float4* xin = (const float4*)(x + (size_t)tile * BM * C2d);
            float4* xs4 = (float4*)xs;
#pragma unroll
            for (int j = 0; j < (BM*C2d/4)/THREADS; j++)   // 4
                xs4[tid + j*THREADS] = xin[tid + j*THREADS];
        }
        __syncthreads();

        // ---- GEMM: acc[i][m] = f32x2 (re@n=m*128+tn, im@n=m*128+tn+64) over k=0..127
        unsigned long long acc[8][3];
#pragma unroll
        for (int i = 0; i < 8; i++)
#pragma unroll
            for (int m = 0; m < 3; m++) acc[i][m] = 0ULL;

        const ulonglong2* ws2u = (const ulonglong2*)ws2;
        const float4* xs4 = (const float4*)xs;
#pragma unroll 4
        for (int k4 = 0; k4 < 32; k4++){
            ulonglong2 wA[3], wB[3];
#pragma unroll
            for (int m = 0; m < 3; m++){
                int base = ((m*64 + tn) << 6);
                wA[m] = ws2u[base + ((2*k4  ) ^ sw)];
                wB[m] = ws2u[base + ((2*k4+1) ^ sw)];
            }
#pragma unroll
            for (int i = 0; i < 8; i++){
                float4 xa = xs4[(rg*8 + i)*32 + k4];
                unsigned long long x0 = splat2(xa.x), x1 = splat2(xa.y);
                unsigned long long x2 = splat2(xa.z), x3 = splat2(xa.w);
#pragma unroll
                for (int m = 0; m < 3; m++){
                    acc[i][m] = fma2(x0, wA[m].x, acc[i][m]);
                    acc[i][m] = fma2(x1, wA[m].y, acc[i][m]);
                    acc[i][m] = fma2(x2, wB[m].x, acc[i][m]);
                    acc[i][m] = fma2(x3, wB[m].y, acc[i][m]);
                }
            }
        }

        // ---- Epilogue: gates + 16-step complex-diagonal recurrence (row-paired f32x2)
        const int rowBase = tile*BM + rg*8;
#pragma unroll
        for (int ip = 0; ip < 4; ip++){
            float AR[2], AI[2], FR[2], FI[2], IR[2], II[2];
#pragma unroll
            for (int s = 0; s < 2; s++){
                const int i = 2*ip + s;
                const int m = rowBase + i;
                float fre, fim, ire, iim, dre, dim_;
                unpack2(acc[i][0], fre, fim);
                unpack2(acc[i][1], ire, iim);
                unpack2(acc[i][2], dre, dim_);
                float fg_r = sigmoidf_(fre + bf_lo + 2.0f);
                float fg_i = sigmoidf_(fim + bf_hi + 2.0f);
                float ig_r = sigmoidf_(ire + bi_lo);
                float ig_i = sigmoidf_(iim + bi_hi);
                float dl_r = softplusf_(dre + bd_lo) * 0.1f;
                float dl_i = softplusf_(dim_ + bd_hi) * 0.1f;
                float x_r = xs[(rg*8 + i)*128 + tn];
                float x_i = xs[(rg*8 + i)*128 + 64 + tn];
                int aidx = (m & (Hdim*Wdim - 1))*Cdim + tn;
                float Ar = g_Ar[aidx], Aii = g_Ai[aidx];
                float Br = g_Br[aidx], Bii = g_Bi[aidx];
                float Bx_r = Br*x_r - Bii*x_i;
                float Bx_i = Br*x_i + Bii*x_r;
                AR[s] = Ar;  AI[s] = Aii;
                FR[s] = fg_r; FI[s] = fg_i;
                IR[s] = dl_r*ig_r*Bx_r;
                II[s] = dl_i*ig_i*Bx_i;
            }
            unsigned long long AR2  = pack2(AR[0], AR[1]);
            unsigned long long AI2  = pack2(AI[0], AI[1]);
            unsigned long long AIn2 = pack2(-AI[0], -AI[1]);
            unsigned long long FR2  = pack2(FR[0], FR[1]);
            unsigned long long FI2  = pack2(FI[0], FI[1]);
            unsigned long long IR2  = pack2(IR[0], IR[1]);
            unsigned long long II2  = pack2(II[0], II[1]);
            unsigned long long HR2 = 0ULL, HI2 = 0ULL;
#pragma unroll
            for (int t = 0; t < Tsteps; t++){
                unsigned long long tr = fma2(AIn2, HI2, mul2(AR2, HR2)); // Ar*hr - Ai*hi
                unsigned long long ti = fma2(AI2,  HR2, mul2(AR2, HI2)); // Ar*hi + Ai*hr
                HR2 = fma2(FR2, tr, IR2);
                HI2 = fma2(FI2, ti, II2);
            }
            float hr0, hr1, hi0, hi1;
            unpack2(HR2, hr0, hr1);
            unpack2(HI2, hi0, hi1);
            const int m0 = rowBase + 2*ip, m1 = m0 + 1;
            out[(size_t)m0*128 + tn]      = hr0;
            out[(size_t)m0*128 + 64 + tn] = hi0;
            out[(size_t)m1*128 + tn]      = hr1;
            out[(size_t)m1*128 + 64 + tn] = hi1;
        }
    }
}

extern "C" void kernel_launch(void* const* d_in, const int* in_sizes, int n_in,
                              void* d_out, int out_size){
    const float* x      = (const float*)d_in[0];
    const float* Wf     = (const float*)d_in[1];
    const float* bf     = (const float*)d_in[2];
    const float* Wi     = (const float*)d_in[3];
    const float* bi     = (const float*)d_in[4];
    const float* Wd     = (const float*)d_in[5];
    const float* bd     = (const float*)d_in[6];
    const float* A_real = (const float*)d_in[7];
    const float* A_imag = (const float*)d_in[8];
    const float* B_real = (const float*)d_in[9];
    const float* B_imag = (const float*)d_in[10];
    float* out = (float*)d_out;

    // Kernel 0: DFT fields
    dft_kernel<<<dim3(Wdim, Hdim), 64>>>(A_real, A_imag, B_real, B_imag);

    // Kernel 1: persistent fused kernel
    const int smem_bytes = 4*12288*4 + BM*C2d*4;   // 196608 + 32768 = 229376
    cudaFuncSetAttribute(main_kernel, cudaFuncAttributeMaxDynamicSharedMemorySize, smem_bytes);
    int dev = 0, nsm = 148;
    cudaGetDevice(&dev);
    cudaDeviceGetAttribute(&nsm, cudaDevAttrMultiProcessorCount, dev);
    main_kernel<<<nsm, THREADS, smem_bytes>>>(x, Wf, bf, Wi, bi, Wd, bd, out);
}

// round 3
// speedup vs baseline: 1.0791x; 1.0791x over previous
#include <cuda_runtime.h>
#include <cuda_bf16.h>
#include <math.h>

#define Bdim 16
#define Hdim 128
#define Wdim 128
#define Cdim 64
#define C2d  128
#define Tsteps 16
#define Mrows (Bdim*Hdim*Wdim)      // 262144
#define BM 32
#define NTILES (Mrows/BM)           // 8192
#define THREADS 512

// DFT'd (and A-scaled) convolution fields, layout [h][w][c]
__device__ float g_Ar[Hdim*Wdim*Cdim];
__device__ float g_Ai[Hdim*Wdim*Cdim];
__device__ float g_Br[Hdim*Wdim*Cdim];
__device__ float g_Bi[Hdim*Wdim*Cdim];

// Stage-1 partials: P[v][p][c], complex, for A and B
__device__ float g_PAr[Wdim*7*Cdim];
__device__ float g_PAi[Wdim*7*Cdim];
__device__ float g_PBr[Wdim*7*Cdim];
__device__ float g_PBi[Wdim*7*Cdim];

// ---------------- f32x2 helpers (sm_100+) ----------------
static __device__ __forceinline__ unsigned long long pack2(float lo, float hi){
    unsigned long long r; asm("mov.b64 %0, {%1, %2};" : "=l"(r) : "f"(lo), "f"(hi)); return r;
}
static __device__ __forceinline__ void unpack2(unsigned long long v, float& lo, float& hi){
    asm("mov.b64 {%0, %1}, %2;" : "=f"(lo), "=f"(hi) : "l"(v));
}
static __device__ __forceinline__ unsigned long long fma2(unsigned long long a, unsigned long long b, unsigned long long c){
    unsigned long long d; asm("fma.rn.f32x2 %0, %1, %2, %3;" : "=l"(d) : "l"(a), "l"(b), "l"(c)); return d;
}
static __device__ __forceinline__ unsigned long long mul2(unsigned long long a, unsigned long long b){
    unsigned long long d; asm("mul.rn.f32x2 %0, %1, %2;" : "=l"(d) : "l"(a), "l"(b)); return d;
}
static __device__ __forceinline__ float sigmoidf_(float x){
    return __fdividef(1.0f, 1.0f + __expf(-x));
}
static __device__ __forceinline__ float softplusf_(float x){
    return fmaxf(x, 0.0f) + __logf(1.0f + __expf(-fabsf(x)));
}

// ---------------- DFT stage 1: row DFT over q ----------------
// P[v][p][c] = sum_q kern[c][p][q] * exp(-2pi i v(q+60)/128)
// grid = 128 (v), 64 threads (c). Thread c reads only its own 49-tap row
// (no cross-thread sharing -> direct LDG, L2-resident after first block).
__global__ void dft_stage1(const float* __restrict__ A_real, const float* __restrict__ A_imag,
                           const float* __restrict__ B_real, const float* __restrict__ B_imag){
    const int c = threadIdx.x;
    const int v = blockIdx.x;
    float twr[7], twi[7];
#pragma unroll
    for (int q = 0; q < 7; q++){
        int idx = (v * (q + 60)) & 127;
        float s, co; sincospif((float)idx / 64.0f, &s, &co);
        twr[q] = co; twi[q] = -s;
    }
#pragma unroll
    for (int p = 0; p < 7; p++){
        float par = 0.f, pai = 0.f, pbr = 0.f, pbi = 0.f;
#pragma unroll
        for (int q = 0; q < 7; q++){
            int ki = c*49 + p*7 + q;
            float ar = A_real[ki], ai = A_imag[ki];
            float br = B_real[ki], bi = B_imag[ki];
            par += ar*twr[q] - ai*twi[q];  pai += ar*twi[q] + ai*twr[q];
            pbr += br*twr[q] - bi*twi[q];  pbi += br*twi[q] + bi*twr[q];
        }
        int o = (v*7 + p)*64 + c;
        g_PAr[o] = par; g_PAi[o] = pai;
        g_PBr[o] = pbr; g_PBi[o] = pbi;
    }
}

// ---------------- DFT stage 2: column DFT over p + A stabilization ----------------
// grid = (2, 128): u = blockIdx.y, v in [blockIdx.x*64, +64). 256 threads.
__global__ void dft_stage2(){
    const int u = blockIdx.y;
    const int vbase = blockIdx.x * 64;
    float eur[7], eui[7];
#pragma unroll
    for (int p = 0; p < 7; p++){
        int idx = (u * (p + 60)) & 127;
        float s, co; sincospif((float)idx / 64.0f, &s, &co);
        eur[p] = co; eui[p] = -s;
    }
    for (int it = 0; it < 16; it++){
        int idx = threadIdx.x + it*256;          // 0..4095
        int vl = idx >> 6;
        int c  = idx & 63;
        int v  = vbase + vl;
        float fra = 0.f, fia = 0.f, frb = 0.f, fib = 0.f;
#pragma unroll
        for (int p = 0; p < 7; p++){
            int o = (v*7 + p)*64 + c;
            float par = g_PAr[o], pai = g_PAi[o];
            float pbr = g_PBr[o], pbi = g_PBi[o];
            fra += eur[p]*par - eui[p]*pai;  fia += eur[p]*pai + eui[p]*par;
            frb += eur[p]*pbr - eui[p]*pbi;  fib += eur[p]*pbi + eui[p]*pbr;
        }
        float mag = sqrtf(fra*fra + fia*fia + 1e-8f);
        float sc  = 0.95f * sigmoidf_(mag) / (mag + 1e-8f);
        int o = (u*Wdim + v)*Cdim + c;
        g_Ar[o] = fra * sc;  g_Ai[o] = fia * sc;
        g_Br[o] = frb;       g_Bi[o] = fib;
    }
}

// ---------------- Main: persistent fused gates-GEMM + recurrence ----------------
// smem: ws2 [m][k2][c] float4 = 192KB (conflict-free), xs2 = 32x128 duplicated f32 pairs = 32KB
__global__ void __launch_bounds__(THREADS, 1)
main_kernel(const float* __restrict__ x,
            const float* __restrict__ Wf, const float* __restrict__ bf,
            const float* __restrict__ Wi, const float* __restrict__ bip,
            const float* __restrict__ Wd, const float* __restrict__ bd,
            float* __restrict__ out){
    extern __shared__ float smem[];
    float4* ws2 = (float4*)smem;                         // 12288 float4 = 192KB
    unsigned long long* xs2 = (unsigned long long*)(smem + 4*12288);  // 4096 x 8B = 32KB

    const int tid = threadIdx.x;
    const int tn  = tid & 63;                // channel 0..63
    const int rg  = tid >> 6;                // row group 0..7 (4 rows each)

    // Stage weights once per persistent block, layout [m][k2][c]:
    // ws2[(m*64 + k2)*64 + c] = {Wm[2k2][c], Wm[2k2][c+64], Wm[2k2+1][c], Wm[2k2+1][c+64]}
    for (int idx = tid; idx < 3*64*64; idx += THREADS){
        int c  = idx & 63;
        int k2 = (idx >> 6) & 63;
        int m  = idx >> 12;
        const float* Wm = (m == 0) ? Wf : ((m == 1) ? Wi : Wd);
        float4 v;
        v.x = Wm[(2*k2  )*128 + c];
        v.y = Wm[(2*k2  )*128 + c + 64];
        v.z = Wm[(2*k2+1)*128 + c];
        v.w = Wm[(2*k2+1)*128 + c + 64];
        ws2[idx] = v;
    }

    const float bf_lo = bf[tn],  bf_hi = bf[tn+64];
    const float bi_lo = bip[tn], bi_hi = bip[tn+64];
    const float bd_lo = bd[tn],  bd_hi = bd[tn+64];

    const ulonglong2* ws2u = (const ulonglong2*)ws2;
    const ulonglong2* xs2u2 = (const ulonglong2*)xs2;
    const float* xsf = (const float*)xs2;

    for (int tile = blockIdx.x; tile < NTILES; tile += gridDim.x){
        __syncthreads();   // also covers first-iteration ws2 readiness
        // Load X tile (32 rows x 128 floats) and store duplicated {x,x} pairs
        {
            const float4* xin = (const float4*)(x + (size_t)tile * BM * C2d);
            ulonglong2* xo = (ulonglong2*)xs2;
#pragma unroll
            for (int j = 0; j < 2; j++){
                int e4 = tid + j*THREADS;          // float4 index, 0..1023
                float4 v = xin[e4];
                xo[e4*2    ] = make_ulonglong2(pack2(v.x, v.x), pack2(v.y, v.y));
                xo[e4*2 + 1] = make_ulonglong2(pack2(v.z, v.z), pack2(v.w, v.w));
            }
        }
        __syncthreads();

        // ---- GEMM: acc[i][m] = f32x2 (re@col=tn, im@col=tn+64), k=0..127
        unsigned long long acc[4][3];
#pragma unroll
        for (int i = 0; i < 4; i++)
#pragma unroll
            for (int m = 0; m < 3; m++) acc[i][m] = 0ULL;

#pragma unroll 4
        for (int k4 = 0; k4 < 32; k4++){
            ulonglong2 wA[3], wB[3];
#pragma unroll
            for (int m = 0; m < 3; m++){
                wA[m] = ws2u[(m*64 + 2*k4    )*64 + tn];
                wB[m] = ws2u[(m*64 + 2*k4 + 1)*64 + tn];
            }
#pragma unroll
            for (int i = 0; i < 4; i++){
                int row = rg*4 + i;
                ulonglong2 xv0 = xs2u2[row*64 + 2*k4];      // {dup x[4k4], dup x[4k4+1]}
                ulonglong2 xv1 = xs2u2[row*64 + 2*k4 + 1];  // {dup x[4k4+2], dup x[4k4+3]}
#pragma unroll
                for (int m = 0; m < 3; m++){
                    acc[i][m] = fma2(xv0.x, wA[m].x, acc[i][m]);
                    acc[i][m] = fma2(xv0.y, wA[m].y, acc[i][m]);
                    acc[i][m] = fma2(xv1.x, wB[m].x, acc[i][m]);
                    acc[i][m] = fma2(xv1.y, wB[m].y, acc[i][m]);
                }
            }
        }

        // ---- Epilogue: gates + 16-step complex-diagonal recurrence (row-paired f32x2)
        const int rowBase = tile*BM + rg*4;
#pragma unroll
        for (int ip = 0; ip < 2; ip++){
            float AR[2], AI[2], FR[2], FI[2], IR[2], II[2];
#pragma unroll
            for (int s = 0; s < 2; s++){
                const int i = 2*ip + s;
                const int m = rowBase + i;
                float fre, fim, ire, iim, dre, dim_;
                unpack2(acc[i][0], fre, fim);
                unpack2(acc[i][1], ire, iim);
                unpack2(acc[i][2], dre, dim_);
                float fg_r = sigmoidf_(fre + bf_lo + 2.0f);
                float fg_i = sigmoidf_(fim + bf_hi + 2.0f);
                float ig_r = sigmoidf_(ire + bi_lo);
                float ig_i = sigmoidf_(iim + bi_hi);
                float dl_r = softplusf_(dre + bd_lo) * 0.1f;
                float dl_i = softplusf_(dim_ + bd_hi) * 0.1f;
                int lrow = rg*4 + i;
                float x_r = xsf[(lrow*128 + tn) * 2];
                float x_i = xsf[(lrow*128 + 64 + tn) * 2];
                int aidx = (m & (Hdim*Wdim - 1))*Cdim + tn;
                float Ar = g_Ar[aidx], Aii = g_Ai[aidx];
                float Br = g_Br[aidx], Bii = g_Bi[aidx];
                float Bx_r = Br*x_r - Bii*x_i;
                float Bx_i = Br*x_i + Bii*x_r;
                AR[s] = Ar;  AI[s] = Aii;
                FR[s] = fg_r; FI[s] = fg_i;
                IR[s] = dl_r*ig_r*Bx_r;
                II[s] = dl_i*ig_i*Bx_i;
            }
            unsigned long long AR2  = pack2(AR[0], AR[1]);
            unsigned long long AI2  = pack2(AI[0], AI[1]);
            unsigned long long AIn2 = pack2(-AI[0], -AI[1]);
            unsigned long long FR2  = pack2(FR[0], FR[1]);
            unsigned long long FI2  = pack2(FI[0], FI[1]);
            unsigned long long IR2  = pack2(IR[0], IR[1]);
            unsigned long long II2  = pack2(II[0], II[1]);
            unsigned long long HR2 = 0ULL, HI2 = 0ULL;
#pragma unroll
            for (int t = 0; t < Tsteps; t++){
                unsigned long long tr = fma2(AIn2, HI2, mul2(AR2, HR2)); // Ar*hr - Ai*hi
                unsigned long long ti = fma2(AI2,  HR2, mul2(AR2, HI2)); // Ar*hi + Ai*hr
                HR2 = fma2(FR2, tr, IR2);
                HI2 = fma2(FI2, ti, II2);
            }
            float hr0, hr1, hi0, hi1;
            unpack2(HR2, hr0, hr1);
            unpack2(HI2, hi0, hi1);
            const int m0 = rowBase + 2*ip, m1 = m0 + 1;
            out[(size_t)m0*128 + tn]      = hr0;
            out[(size_t)m0*128 + 64 + tn] = hi0;
            out[(size_t)m1*128 + tn]      = hr1;
            out[(size_t)m1*128 + 64 + tn] = hi1;
        }
    }
}

extern "C" void kernel_launch(void* const* d_in, const int* in_sizes, int n_in,
                              void* d_out, int out_size){
    const float* x      = (const float*)d_in[0];
    const float* Wf     = (const float*)d_in[1];
    const float* bf     = (const float*)d_in[2];
    const float* Wi     = (const float*)d_in[3];
    const float* bi     = (const float*)d_in[4];
    const float* Wd     = (const float*)d_in[5];
    const float* bd     = (const float*)d_in[6];
    const float* A_real = (const float*)d_in[7];
    const float* A_imag = (const float*)d_in[8];
    const float* B_real = (const float*)d_in[9];
    const float* B_imag = (const float*)d_in[10];
    float* out = (float*)d_out;

    dft_stage1<<<Wdim, 64>>>(A_real, A_imag, B_real, B_imag);
    dft_stage2<<<dim3(2, Hdim), 256>>>();

    const int smem_bytes = 4*12288*4 + BM*C2d*8;   // 196608 + 32768 = 229376
    cudaFuncSetAttribute(main_kernel, cudaFuncAttributeMaxDynamicSharedMemorySize, smem_bytes);
    int dev = 0, nsm = 148;
    cudaGetDevice(&dev);
    cudaDeviceGetAttribute(&nsm, cudaDevAttrMultiProcessorCount, dev);
    main_kernel<<<nsm, THREADS, smem_bytes>>>(x, Wf, bf, Wi, bi, Wd, bd, out);
}

// round 4
// speedup vs baseline: 1.3322x; 1.2346x over previous
#include <cuda_runtime.h>
#include <cuda_bf16.h>
#include <math.h>

#define Bdim 16
#define Hdim 128
#define Wdim 128
#define Cdim 64
#define C2d  128
#define Tsteps 16
#define Mrows (Bdim*Hdim*Wdim)      // 262144
#define BM 64
#define NTILES (Mrows/BM)           // 4096
#define THREADS 512

// DFT'd (and A-scaled) convolution fields, layout [h][w][c]
__device__ float g_Ar[Hdim*Wdim*Cdim];
__device__ float g_Ai[Hdim*Wdim*Cdim];
__device__ float g_Br[Hdim*Wdim*Cdim];
__device__ float g_Bi[Hdim*Wdim*Cdim];

// Stage-1 partials: P[v][p][c], complex, for A and B
__device__ float g_PAr[Wdim*7*Cdim];
__device__ float g_PAi[Wdim*7*Cdim];
__device__ float g_PBr[Wdim*7*Cdim];
__device__ float g_PBi[Wdim*7*Cdim];

// ---------------- f32x2 helpers (sm_100+) ----------------
static __device__ __forceinline__ unsigned long long splat2(float x){
    unsigned long long r; asm("mov.b64 %0, {%1, %1};" : "=l"(r) : "f"(x)); return r;
}
static __device__ __forceinline__ unsigned long long pack2(float lo, float hi){
    unsigned long long r; asm("mov.b64 %0, {%1, %2};" : "=l"(r) : "f"(lo), "f"(hi)); return r;
}
static __device__ __forceinline__ void unpack2(unsigned long long v, float& lo, float& hi){
    asm("mov.b64 {%0, %1}, %2;" : "=f"(lo), "=f"(hi) : "l"(v));
}
static __device__ __forceinline__ unsigned long long fma2(unsigned long long a, unsigned long long b, unsigned long long c){
    unsigned long long d; asm("fma.rn.f32x2 %0, %1, %2, %3;" : "=l"(d) : "l"(a), "l"(b), "l"(c)); return d;
}
static __device__ __forceinline__ unsigned long long mul2(unsigned long long a, unsigned long long b){
    unsigned long long d; asm("mul.rn.f32x2 %0, %1, %2;" : "=l"(d) : "l"(a), "l"(b)); return d;
}
static __device__ __forceinline__ float sigmoidf_(float x){
    return __fdividef(1.0f, 1.0f + __expf(-x));
}
static __device__ __forceinline__ float softplusf_(float x){
    return fmaxf(x, 0.0f) + __logf(1.0f + __expf(-fabsf(x)));
}

// ---------------- DFT stage 1: row DFT over q ----------------
__global__ void dft_stage1(const float* __restrict__ A_real, const float* __restrict__ A_imag,
                           const float* __restrict__ B_real, const float* __restrict__ B_imag){
    const int c = threadIdx.x;
    const int v = blockIdx.x;
    float twr[7], twi[7];
#pragma unroll
    for (int q = 0; q < 7; q++){
        int idx = (v * (q + 60)) & 127;
        float s, co; sincospif((float)idx / 64.0f, &s, &co);
        twr[q] = co; twi[q] = -s;
    }
#pragma unroll
    for (int p = 0; p < 7; p++){
        float par = 0.f, pai = 0.f, pbr = 0.f, pbi = 0.f;
#pragma unroll
        for (int q = 0; q < 7; q++){
            int ki = c*49 + p*7 + q;
            float ar = A_real[ki], ai = A_imag[ki];
            float br = B_real[ki], bi = B_imag[ki];
            par += ar*twr[q] - ai*twi[q];  pai += ar*twi[q] + ai*twr[q];
            pbr += br*twr[q] - bi*twi[q];  pbi += br*twi[q] + bi*twr[q];
        }
        int o = (v*7 + p)*64 + c;
        g_PAr[o] = par; g_PAi[o] = pai;
        g_PBr[o] = pbr; g_PBi[o] = pbi;
    }
}

// ---------------- DFT stage 2: column DFT over p + A stabilization ----------------
__global__ void dft_stage2(){
    const int u = blockIdx.y;
    const int vbase = blockIdx.x * 64;
    float eur[7], eui[7];
#pragma unroll
    for (int p = 0; p < 7; p++){
        int idx = (u * (p + 60)) & 127;
        float s, co; sincospif((float)idx / 64.0f, &s, &co);
        eur[p] = co; eui[p] = -s;
    }
    for (int it = 0; it < 16; it++){
        int idx = threadIdx.x + it*256;          // 0..4095
        int vl = idx >> 6;
        int c  = idx & 63;
        int v  = vbase + vl;
        float fra = 0.f, fia = 0.f, frb = 0.f, fib = 0.f;
#pragma unroll
        for (int p = 0; p < 7; p++){
            int o = (v*7 + p)*64 + c;
            float par = g_PAr[o], pai = g_PAi[o];
            float pbr = g_PBr[o], pbi = g_PBi[o];
            fra += eur[p]*par - eui[p]*pai;  fia += eur[p]*pai + eui[p]*par;
            frb += eur[p]*pbr - eui[p]*pbi;  fib += eur[p]*pbi + eui[p]*pbr;
        }
        float mag = sqrtf(fra*fra + fia*fia + 1e-8f);
        float sc  = 0.95f * sigmoidf_(mag) / (mag + 1e-8f);
        int o = (u*Wdim + v)*Cdim + c;
        g_Ar[o] = fra * sc;  g_Ai[o] = fia * sc;
        g_Br[o] = frb;       g_Bi[o] = fib;
    }
}

// ---------------- Main: persistent fused gates-GEMM + recurrence ----------------
// smem: ws2 [m][k2][c] float4 = 192KB (conflict-free LDS.128), xs = 64x128 f32 = 32KB
__global__ void __launch_bounds__(THREADS, 1)
main_kernel(const float* __restrict__ x,
            const float* __restrict__ Wf, const float* __restrict__ bf,
            const float* __restrict__ Wi, const float* __restrict__ bip,
            const float* __restrict__ Wd, const float* __restrict__ bd,
            float* __restrict__ out){
    extern __shared__ float smem[];
    float4* ws2 = (float4*)smem;             // 12288 float4 = 192KB
    float*  xs  = smem + 4*12288;            // 8192 floats = 32KB

    const int tid = threadIdx.x;
    const int tn  = tid & 63;                // channel 0..63
    const int rg  = tid >> 6;                // row group 0..7 (8 rows each)

    // Stage weights once per persistent block, layout [m][k2][c]:
    // ws2[(m*64 + k2)*64 + c] = {Wm[2k2][c], Wm[2k2][c+64], Wm[2k2+1][c], Wm[2k2+1][c+64]}
    for (int idx = tid; idx < 3*64*64; idx += THREADS){
        int c  = idx & 63;
        int k2 = (idx >> 6) & 63;
        int m  = idx >> 12;
        const float* Wm = (m == 0) ? Wf : ((m == 1) ? Wi : Wd);
        float4 v;
        v.x = Wm[(2*k2  )*128 + c];
        v.y = Wm[(2*k2  )*128 + c + 64];
        v.z = Wm[(2*k2+1)*128 + c];
        v.w = Wm[(2*k2+1)*128 + c + 64];
        ws2[idx] = v;
    }

    const float bf_lo = bf[tn],  bf_hi = bf[tn+64];
    const float bi_lo = bip[tn], bi_hi = bip[tn+64];
    const float bd_lo = bd[tn],  bd_hi = bd[tn+64];

    const ulonglong2* ws2u = (const ulonglong2*)ws2;

    for (int tile = blockIdx.x; tile < NTILES; tile += gridDim.x){
        __syncthreads();   // also covers first-iteration ws2 readiness
        // Load X tile (64 rows x 128 floats), coalesced float4
        {
            const float4* xin = (const float4*)(x + (size_t)tile * BM * C2d);
            float4* xs4 = (float4*)xs;
#pragma unroll
            for (int j = 0; j < (BM*C2d/4)/THREADS; j++)   // 4
                xs4[tid + j*THREADS] = xin[tid + j*THREADS];
        }
        __syncthreads();

        // ---- GEMM: acc[i][m] = f32x2 (re@col=tn, im@col=tn+64), k=0..127
        unsigned long long acc[8][3];
#pragma unroll
        for (int i = 0; i < 8; i++)
#pragma unroll
            for (int m = 0; m < 3; m++) acc[i][m] = 0ULL;

        const float4* xs4 = (const float4*)xs;
#pragma unroll 4
        for (int k4 = 0; k4 < 32; k4++){
            ulonglong2 wA[3], wB[3];
#pragma unroll
            for (int m = 0; m < 3; m++){
                wA[m] = ws2u[(m*64 + 2*k4    )*64 + tn];
                wB[m] = ws2u[(m*64 + 2*k4 + 1)*64 + tn];
            }
#pragma unroll
            for (int i = 0; i < 8; i++){
                float4 xa = xs4[(rg*8 + i)*32 + k4];       // broadcast within warp
                unsigned long long x0 = splat2(xa.x), x1 = splat2(xa.y);
                unsigned long long x2 = splat2(xa.z), x3 = splat2(xa.w);
#pragma unroll
                for (int m = 0; m < 3; m++){
                    acc[i][m] = fma2(x0, wA[m].x, acc[i][m]);
                    acc[i][m] = fma2(x1, wA[m].y, acc[i][m]);
                    acc[i][m] = fma2(x2, wB[m].x, acc[i][m]);
                    acc[i][m] = fma2(x3, wB[m].y, acc[i][m]);
                }
            }
        }

        // ---- Epilogue: gates + 16-step complex-diagonal recurrence (row-paired f32x2)
        const int rowBase = tile*BM + rg*8;
#pragma unroll
        for (int ip = 0; ip < 4; ip++){
            float AR[2], AI[2], FR[2], FI[2], IR[2], II[2];
#pragma unroll
            for (int s = 0; s < 2; s++){
                const int i = 2*ip + s;
                const int m = rowBase + i;
                float fre, fim, ire, iim, dre, dim_;
                unpack2(acc[i][0], fre, fim);
                unpack2(acc[i][1], ire, iim);
                unpack2(acc[i][2], dre, dim_);
                float fg_r = sigmoidf_(fre + bf_lo + 2.0f);
                float fg_i = sigmoidf_(fim + bf_hi + 2.0f);
                float ig_r = sigmoidf_(ire + bi_lo);
                float ig_i = sigmoidf_(iim + bi_hi);
                float dl_r = softplusf_(dre + bd_lo) * 0.1f;
                float dl_i = softplusf_(dim_ + bd_hi) * 0.1f;
                float x_r = xs[(rg*8 + i)*128 + tn];
                float x_i = xs[(rg*8 + i)*128 + 64 + tn];
                int aidx = (m & (Hdim*Wdim - 1))*Cdim + tn;
                float Ar = g_Ar[aidx], Aii = g_Ai[aidx];
                float Br = g_Br[aidx], Bii = g_Bi[aidx];
                float Bx_r = Br*x_r - Bii*x_i;
                float Bx_i = Br*x_i + Bii*x_r;
                AR[s] = Ar;  AI[s] = Aii;
                FR[s] = fg_r; FI[s] = fg_i;
                IR[s] = dl_r*ig_r*Bx_r;
                II[s] = dl_i*ig_i*Bx_i;
            }
            unsigned long long AR2  = pack2(AR[0], AR[1]);
            unsigned long long AI2  = pack2(AI[0], AI[1]);
            unsigned long long AIn2 = pack2(-AI[0], -AI[1]);
            unsigned long long FR2  = pack2(FR[0], FR[1]);
            unsigned long long FI2  = pack2(FI[0], FI[1]);
            unsigned long long IR2  = pack2(IR[0], IR[1]);
            unsigned long long II2  = pack2(II[0], II[1]);
            unsigned long long HR2 = 0ULL, HI2 = 0ULL;
#pragma unroll
            for (int t = 0; t < Tsteps; t++){
                unsigned long long tr = fma2(AIn2, HI2, mul2(AR2, HR2)); // Ar*hr - Ai*hi
                unsigned long long ti = fma2(AI2,  HR2, mul2(AR2, HI2)); // Ar*hi + Ai*hr
                HR2 = fma2(FR2, tr, IR2);
                HI2 = fma2(FI2, ti, II2);
            }
            float hr0, hr1, hi0, hi1;
            unpack2(HR2, hr0, hr1);
            unpack2(HI2, hi0, hi1);
            const int m0 = rowBase + 2*ip, m1 = m0 + 1;
            out[(size_t)m0*128 + tn]      = hr0;
            out[(size_t)m0*128 + 64 + tn] = hi0;
            out[(size_t)m1*128 + tn]      = hr1;
            out[(size_t)m1*128 + 64 + tn] = hi1;
        }
    }
}

extern "C" void kernel_launch(void* const* d_in, const int* in_sizes, int n_in,
                              void* d_out, int out_size){
    const float* x      = (const float*)d_in[0];
    const float* Wf     = (const float*)d_in[1];
    const float* bf     = (const float*)d_in[2];
    const float* Wi     = (const float*)d_in[3];
    const float* bi     = (const float*)d_in[4];
    const float* Wd     = (const float*)d_in[5];
    const float* bd     = (const float*)d_in[6];
    const float* A_real = (const float*)d_in[7];
    const float* A_imag = (const float*)d_in[8];
    const float* B_real = (const float*)d_in[9];
    const float* B_imag = (const float*)d_in[10];
    float* out = (float*)d_out;

    dft_stage1<<<Wdim, 64>>>(A_real, A_imag, B_real, B_imag);
    dft_stage2<<<dim3(2, Hdim), 256>>>();

    const int smem_bytes = 4*12288*4 + BM*C2d*4;   // 196608 + 32768 = 229376
    cudaFuncSetAttribute(main_kernel, cudaFuncAttributeMaxDynamicSharedMemorySize, smem_bytes);
    int dev = 0, nsm = 148;
    cudaGetDevice(&dev);
    cudaDeviceGetAttribute(&nsm, cudaDevAttrMultiProcessorCount, dev);
    main_kernel<<<nsm, THREADS, smem_bytes>>>(x, Wf, bf, Wi, bi, Wd, bd, out);
}

// round 8
// speedup vs baseline: 2.6481x; 1.9877x over previous
#include <cuda_runtime.h>
#include <stdint.h>
#include <math.h>

#define Tsteps 16
#define NT 4096              // tiles of 64 rows (262144/64)
#define THREADS 512

// Transposed DFT fields: [c][pos], pos = u*128+v
__device__ float g_ArT[64*16384];
__device__ float g_AiT[64*16384];
__device__ float g_BrT[64*16384];
__device__ float g_BiT[64*16384];
// Stage-1 partials, layout [p][c][v]
__device__ float g_PAr[7*64*128];
__device__ float g_PAi[7*64*128];
__device__ float g_PBr[7*64*128];
__device__ float g_PBi[7*64*128];

// ---------------- helpers ----------------
static __device__ __forceinline__ unsigned long long pack2(float lo, float hi){
    unsigned long long r; asm("mov.b64 %0, {%1, %2};" : "=l"(r) : "f"(lo), "f"(hi)); return r;
}
static __device__ __forceinline__ void unpack2(unsigned long long v, float& lo, float& hi){
    asm("mov.b64 {%0, %1}, %2;" : "=f"(lo), "=f"(hi) : "l"(v));
}
static __device__ __forceinline__ unsigned long long fma2(unsigned long long a, unsigned long long b, unsigned long long c){
    unsigned long long d; asm("fma.rn.f32x2 %0, %1, %2, %3;" : "=l"(d) : "l"(a), "l"(b), "l"(c)); return d;
}
static __device__ __forceinline__ float sigmoidf_(float x){
    return __fdividef(1.0f, 1.0f + __expf(-x));
}
static __device__ __forceinline__ float softplusf_(float x){
    return fmaxf(x, 0.0f) + __logf(1.0f + __expf(-fabsf(x)));
}
static __device__ __forceinline__ uint32_t tf32_(float f){
    uint32_t r; asm("cvt.rna.tf32.f32 %0, %1;" : "=r"(r) : "f"(f)); return r;
}
static __device__ __forceinline__ void mma_tf32(float* d, const uint32_t* a, uint32_t b0, uint32_t b1){
    asm volatile("mma.sync.aligned.m16n8k8.row.col.f32.tf32.tf32.f32 "
        "{%0,%1,%2,%3}, {%4,%5,%6,%7}, {%8,%9}, {%0,%1,%2,%3};"
        : "+f"(d[0]), "+f"(d[1]), "+f"(d[2]), "+f"(d[3])
        : "r"(a[0]), "r"(a[1]), "r"(a[2]), "r"(a[3]), "r"(b0), "r"(b1));
}

// ---------------- DFT stage 1: row DFT over q, out [p][c][v] ----------------
__global__ void dft_stage1(const float* __restrict__ A_real, const float* __restrict__ A_imag,
                           const float* __restrict__ B_real, const float* __restrict__ B_imag){
    const int c = threadIdx.x;
    const int v = blockIdx.x;
    float twr[7], twi[7];
#pragma unroll
    for (int q = 0; q < 7; q++){
        int idx = (v * (q + 60)) & 127;
        float s, co; sincospif((float)idx / 64.0f, &s, &co);
        twr[q] = co; twi[q] = -s;
    }
#pragma unroll
    for (int p = 0; p < 7; p++){
        float par = 0.f, pai = 0.f, pbr = 0.f, pbi = 0.f;
#pragma unroll
        for (int q = 0; q < 7; q++){
            int ki = c*49 + p*7 + q;
            float ar = A_real[ki], ai = A_imag[ki];
            float br = B_real[ki], bi = B_imag[ki];
            par += ar*twr[q] - ai*twi[q];  pai += ar*twi[q] + ai*twr[q];
            pbr += br*twr[q] - bi*twi[q];  pbi += br*twi[q] + bi*twr[q];
        }
        int o = (p*64 + c)*128 + v;
        g_PAr[o] = par; g_PAi[o] = pai;
        g_PBr[o] = pbr; g_PBi[o] = pbi;
    }
}

// ---------------- DFT stage 2: column DFT over p + stabilization, transposed out ----------------
__global__ void dft_stage2(){
    const int u = blockIdx.x;
    float eur[7], eui[7];
#pragma unroll
    for (int p = 0; p < 7; p++){
        int idx = (u * (p + 60)) & 127;
        float s, co; sincospif((float)idx / 64.0f, &s, &co);
        eur[p] = co; eui[p] = -s;
    }
    for (int it = 0; it < 16; it++){
        int idx = threadIdx.x + it*512;           // 0..8191
        int c = idx >> 7;
        int v = idx & 127;
        float fra = 0.f, fia = 0.f, frb = 0.f, fib = 0.f;
#pragma unroll
        for (int p = 0; p < 7; p++){
            int o = (p*64 + c)*128 + v;
            float par = g_PAr[o], pai = g_PAi[o];
            float pbr = g_PBr[o], pbi = g_PBi[o];
            fra += eur[p]*par - eui[p]*pai;  fia += eur[p]*pai + eui[p]*par;
            frb += eur[p]*pbr - eui[p]*pbi;  fib += eur[p]*pbi + eui[p]*pbr;
        }
        float mag = sqrtf(fra*fra + fia*fia + 1e-8f);
        float sc  = 0.95f * sigmoidf_(mag) / (mag + 1e-8f);
        int o = c*16384 + u*128 + v;
        g_ArT[o] = fra * sc;  g_AiT[o] = fia * sc;
        g_BrT[o] = frb;       g_BiT[o] = fib;
    }
}

// ---------------- Main: persistent mma.sync tf32 GEMM + fused SSM epilogue ----------------
// SMEM: Ws = 192KB B-fragments (tf32 pairs, persistent), As = 32KB (A-frags / exact-x / h)
// Warp (mg = w&1, nq = w>>1): rows mg*32+mb*16+..., channels 8nq+4nb+(l&3)
__global__ void __launch_bounds__(THREADS, 1)
main_kernel(const float* __restrict__ x,
            const float* __restrict__ Wf, const float* __restrict__ bfp,
            const float* __restrict__ Wi, const float* __restrict__ bip,
            const float* __restrict__ Wd, const float* __restrict__ bdp,
            float* __restrict__ out){
    extern __shared__ char smem[];
    uint2* Ws = (uint2*)smem;                          // 3*16*16*32 = 24576 uint2 = 192KB
    uint32_t* Asu = (uint32_t*)(smem + 196608);        // frag scatter view
    uint4*    As4 = (uint4*)(smem + 196608);           // frag read view
    float*    AsX = (float*)(smem + 196608);           // exact x / h view (32KB)

    const int tid = threadIdx.x;
    const int w = tid >> 5;
    const int l = tid & 31;
    const int mg = w & 1;
    const int nq = w >> 1;

    // ---- one-time: stage W fragments (tf32) ----
    for (int idx = tid; idx < 3*16*16*32; idx += THREADS){
        int lane = idx & 31;
        int ks   = (idx >> 5) & 15;
        int nbG  = (idx >> 9) & 15;
        int g    = idx >> 13;
        int n    = nbG*8 + (lane >> 2);                // j-interleaved output col
        int col  = (n >> 1) + ((n & 1) << 6);          // original output index
        int k0   = ks*8 + (lane & 3);
        const float* Wm = (g == 0) ? Wf : ((g == 1) ? Wi : Wd);
        uint2 bb;
        bb.x = tf32_(Wm[k0*128 + col]);
        bb.y = tf32_(Wm[(k0+4)*128 + col]);
        Ws[idx] = bb;
    }
    // ---- bias registers for this thread's 2 channels ----
    float bfl[2], bfh[2], bil[2], bih[2], bdl[2], bdh[2];
#pragma unroll
    for (int nb = 0; nb < 2; nb++){
        int c = 8*nq + 4*nb + (l & 3);
        bfl[nb] = bfp[c]; bfh[nb] = bfp[c+64];
        bil[nb] = bip[c]; bih[nb] = bip[c+64];
        bdl[nb] = bdp[c]; bdh[nb] = bdp[c+64];
    }
    __syncthreads();

    for (int tile = blockIdx.x; tile < NT; tile += gridDim.x){
        const int base = tile * 64;
        const float4* xin4 = (const float4*)(x + (size_t)base * 128);

        // ---- stage A fragments (tf32, scattered into frag layout) ----
        __syncthreads();   // prior copy-out finished
#pragma unroll
        for (int j = 0; j < 4; j++){
            int e4 = tid + j*THREADS;                  // 0..2047
            int row = e4 >> 5;
            int kq  = e4 & 31;
            float4 v = xin4[e4];
            int ks   = kq >> 1;
            int slot = ((kq & 1) << 1) | ((row >> 3) & 1);
            int lb   = (row & 7) << 2;
            int fragbase = (((row >> 4)*16 + ks) << 5);
            int sx = ks & 7;
            Asu[((fragbase + ((lb+0) ^ sx)) << 2) + slot] = tf32_(v.x);
            Asu[((fragbase + ((lb+1) ^ sx)) << 2) + slot] = tf32_(v.y);
            Asu[((fragbase + ((lb+2) ^ sx)) << 2) + slot] = tf32_(v.z);
            Asu[((fragbase + ((lb+3) ^ sx)) << 2) + slot] = tf32_(v.w);
        }
        __syncthreads();

        // ---- GEMM ----
        float acc[3][2][2][4];
#pragma unroll
        for (int g = 0; g < 3; g++)
#pragma unroll
            for (int mb = 0; mb < 2; mb++)
#pragma unroll
                for (int nb = 0; nb < 2; nb++)
#pragma unroll
                    for (int i = 0; i < 4; i++) acc[g][mb][nb][i] = 0.f;

#pragma unroll
        for (int ks = 0; ks < 16; ks++){
            uint4 Af0 = As4[((mg*2+0)*16 + ks)*32 + (l ^ (ks & 7))];
            uint4 Af1 = As4[((mg*2+1)*16 + ks)*32 + (l ^ (ks & 7))];
#pragma unroll
            for (int g = 0; g < 3; g++){
#pragma unroll
                for (int nb = 0; nb < 2; nb++){
                    uint2 bb = Ws[((g*16 + nq*2 + nb)*16 + ks)*32 + l];
                    mma_tf32(acc[g][0][nb], (const uint32_t*)&Af0, bb.x, bb.y);
                    mma_tf32(acc[g][1][nb], (const uint32_t*)&Af1, bb.x, bb.y);
                }
            }
        }
        __syncthreads();   // done reading As frags

        // ---- stage exact x into AsX (swizzled rows) ----
#pragma unroll
        for (int j = 0; j < 4; j++){
            int e4 = tid + j*THREADS;
            int row = e4 >> 5;
            int c4  = (e4 & 31) << 2;
            float4 v = xin4[e4];
            *(float4*)&AsX[row*128 + (c4 ^ ((row & 7) << 2))] = v;
        }
        __syncthreads();

        // ---- epilogue: gates + 16-step recurrence; h written back into AsX ----
#pragma unroll
        for (int mb = 0; mb < 2; mb++){
#pragma unroll
            for (int nb = 0; nb < 2; nb++){
                const int c   = 8*nq + 4*nb + (l & 3);
                const int rl0 = mg*32 + mb*16 + (l >> 2);
                const int rl1 = rl0 + 8;
                const int p0  = (base + rl0) & 16383;
                const int sw  = c ^ ((l >> 2) << 2);

                const float* af = acc[0][mb][nb];
                const float* ag = acc[1][mb][nb];
                const float* ad = acc[2][mb][nb];

                float fgr0 = sigmoidf_(af[0] + bfl[nb] + 2.0f);
                float fgi0 = sigmoidf_(af[1] + bfh[nb] + 2.0f);
                float fgr1 = sigmoidf_(af[2] + bfl[nb] + 2.0f);
                float fgi1 = sigmoidf_(af[3] + bfh[nb] + 2.0f);
                float igr0 = sigmoidf_(ag[0] + bil[nb]);
                float igi0 = sigmoidf_(ag[1] + bih[nb]);
                float igr1 = sigmoidf_(ag[2] + bil[nb]);
                float igi1 = sigmoidf_(ag[3] + bih[nb]);
                float dlr0 = softplusf_(ad[0] + bdl[nb]) * 0.1f;
                float dli0 = softplusf_(ad[1] + bdh[nb]) * 0.1f;
                float dlr1 = softplusf_(ad[2] + bdl[nb]) * 0.1f;
                float dli1 = softplusf_(ad[3] + bdh[nb]) * 0.1f;

                const float* ArT = g_ArT + (size_t)c*16384 + p0;
                const float* AiT = g_AiT + (size_t)c*16384 + p0;
                const float* BrT = g_BrT + (size_t)c*16384 + p0;
                const float* BiT = g_BiT + (size_t)c*16384 + p0;
                float Ar0 = ArT[0], Ar1 = ArT[8];
                float Ai0 = AiT[0], Ai1 = AiT[8];
                float Br0 = BrT[0], Br1 = BrT[8];
                float Bi0 = BiT[0], Bi1 = BiT[8];

                float xr0 = AsX[rl0*128 + sw];
                float xi0 = AsX[rl0*128 + 64 + sw];
                float xr1 = AsX[rl1*128 + sw];
                float xi1 = AsX[rl1*128 + 64 + sw];

                float Bxr0 = Br0*xr0 - Bi0*xi0, Bxi0 = Br0*xi0 + Bi0*xr0;
                float Bxr1 = Br1*xr1 - Bi1*xi1, Bxi1 = Br1*xi1 + Bi1*xr1;
                float ir0 = dlr0*igr0*Bxr0, ii0 = dli0*igi0*Bxi0;
                float ir1 = dlr1*igr1*Bxr1, ii1 = dli1*igi1*Bxi1;

                unsigned long long A2  = pack2(fgr0*Ar0,  fgr1*Ar1);
                unsigned long long NB2 = pack2(-fgr0*Ai0, -fgr1*Ai1);
                unsigned long long CC2 = pack2(fgi0*Ai0,  fgi1*Ai1);
                unsigned long long DD2 = pack2(fgi0*Ar0,  fgi1*Ar1);
                unsigned long long IR2 = pack2(ir0, ir1);
                unsigned long long II2 = pack2(ii0, ii1);

                unsigned long long HR = 0ULL, HI = 0ULL;
#pragma unroll
                for (int t = 0; t < Tsteps; t++){
                    unsigned long long tr = fma2(NB2, HI, IR2);
                    unsigned long long ti = fma2(CC2, HR, II2);
                    HR = fma2(A2, HR, tr);
                    HI = fma2(DD2, HI, ti);
                }
                float hr0, hr1, hi0, hi1;
                unpack2(HR, hr0, hr1);
                unpack2(HI, hi0, hi1);
                AsX[rl0*128 + sw]      = hr0;
                AsX[rl0*128 + 64 + sw] = hi0;
                AsX[rl1*128 + sw]      = hr1;
                AsX[rl1*128 + 64 + sw] = hi1;
            }
        }
        __syncthreads();

        // ---- coalesced copy-out ----
#pragma unroll
        for (int j = 0; j < 4; j++){
            int e4 = tid + j*THREADS;
            int row = e4 >> 5;
            int c4  = (e4 & 31) << 2;
            float4 v = *(float4*)&AsX[row*128 + (c4 ^ ((row & 7) << 2))];
            *(float4*)(out + (size_t)(base + row)*128 + c4) = v;
        }
    }
}

extern "C" void kernel_launch(void* const* d_in, const int* in_sizes, int n_in,
                              void* d_out, int out_size){
    const float* x      = (const float*)d_in[0];
    const float* Wf     = (const float*)d_in[1];
    const float* bf     = (const float*)d_in[2];
    const float* Wi     = (const float*)d_in[3];
    const float* bi     = (const float*)d_in[4];
    const float* Wd     = (const float*)d_in[5];
    const float* bd     = (const float*)d_in[6];
    const float* A_real = (const float*)d_in[7];
    const float* A_imag = (const float*)d_in[8];
    const float* B_real = (const float*)d_in[9];
    const float* B_imag = (const float*)d_in[10];
    float* out = (float*)d_out;

    dft_stage1<<<128, 64>>>(A_real, A_imag, B_real, B_imag);
    dft_stage2<<<128, 512>>>();

    const int smem_bytes = 196608 + 32768;   // 229376 <= 232448 max
    cudaFuncSetAttribute(main_kernel, cudaFuncAttributeMaxDynamicSharedMemorySize, smem_bytes);
    int dev = 0, nsm = 148;
    cudaGetDevice(&dev);
    cudaDeviceGetAttribute(&nsm, cudaDevAttrMultiProcessorCount, dev);
    main_kernel<<<nsm, THREADS, smem_bytes>>>(x, Wf, bf, Wi, bi, Wd, bd, out);
}